// round 1
// baseline (speedup 1.0000x reference)
#include <cuda_runtime.h>
#include <math.h>

// Problem constants
#define B_ 4
#define T_ 512
#define I_ 512
#define H_ 8
#define D_ 512
#define V_ 32000
#define BT_ (B_*T_)                 // 2048
#define BI_ (B_*I_)                 // 2048
#define BTV_ ((size_t)BT_*V_)       // 65,536,000
#define V4_ (V_/4)                  // 8000 float4 per row
#define CHUNK4_ (V4_/4)             // 2000 float4 per chunk, 4 chunks/row

// ---------------- scratch (__device__ globals; no allocs allowed) -------------
__device__ float g_pexp[BT_*I_];    // exp(z) for first-occurrence slots
__device__ float g_eenc[BI_];       // enc[b,i,:] . W1
__device__ int   g_rep[BI_];        // index of first occurrence of token
__device__ int   g_first[BI_];      // 1 if first occurrence
__device__ int   g_ndist[B_];       // distinct token count per batch
__device__ float g_pg[BT_];         // p_gen
__device__ float g_invden[BT_];     // 1/softmax denominator

// ---------------- kernel 1: per-batch prep (dup grouping + e_enc) ------------
__global__ void prep_kernel(const int* __restrict__ tokens,
                            const float* __restrict__ enc,
                            const float* __restrict__ W) {
    int b = blockIdx.x;
    int tid = threadIdx.x;           // 512 threads
    __shared__ int stok[I_];
    __shared__ int cnt;
    stok[tid] = tokens[b*I_ + tid];
    if (tid == 0) cnt = 0;
    __syncthreads();

    // duplicate grouping: rep = smallest j with same token
    int tok = stok[tid];
    int rep = tid;
    for (int j = 0; j < tid; j++) {
        if (stok[j] == tok) { rep = j; break; }
    }
    g_rep[b*I_ + tid] = rep;
    int first = (rep == tid) ? 1 : 0;
    g_first[b*I_ + tid] = first;
    atomicAdd(&cnt, first);

    // e_enc: warp per row, coalesced
    int wid = tid >> 5, lane = tid & 31;
    for (int k = 0; k < 32; k++) {
        int row = wid*32 + k;
        const float* er = enc + ((size_t)b*I_ + row)*D_;
        float s = 0.f;
        #pragma unroll
        for (int d = lane; d < D_; d += 32) s += er[d]*W[d];
        #pragma unroll
        for (int off = 16; off > 0; off >>= 1)
            s += __shfl_down_sync(0xffffffffu, s, off);
        if (lane == 0) g_eenc[b*I_ + row] = s;
    }
    __syncthreads();
    if (tid == 0) g_ndist[b] = cnt;
}

// ---- kernel 2: per-(b,t) row: head-mean, p_gen, denom, exp table ------------
__global__ void __launch_bounds__(256) row_kernel(
        const float* __restrict__ attn_heads,
        const float* __restrict__ dec,
        const float* __restrict__ tar,
        const float* __restrict__ W,
        const float* __restrict__ bias,
        float* __restrict__ out_pg) {
    int bt = blockIdx.x;
    int b = bt >> 9, t = bt & 511;
    int tid = threadIdx.x;

    __shared__ float sattn[I_];
    __shared__ float sz[I_];
    __shared__ float red_s[256];
    __shared__ float red_d[256];

    const float* base = attn_heads + ((size_t)b*H_*T_*I_) + (size_t)t*I_;
    for (int i = tid; i < I_; i += 256) {
        float s = 0.f;
        #pragma unroll
        for (int h = 0; h < H_; h++) s += base[(size_t)h*T_*I_ + i];
        sattn[i] = s * 0.125f;
        sz[i] = 0.f;
    }
    __syncthreads();

    // scatter grouped z (collisions rare -> shared atomics cheap)
    for (int i = tid; i < I_; i += 256)
        atomicAdd(&sz[g_rep[b*I_ + i]], sattn[i]);

    // p_gen pre-activation partials (sattn read-only here, safe vs sz atomics)
    float ps = 0.f;
    const float* drow = dec + (size_t)bt*D_;
    const float* trow = tar + (size_t)bt*D_;
    for (int d = tid; d < D_; d += 256) {
        ps += sattn[d]*g_eenc[b*I_ + d];
        ps += drow[d]*W[D_ + d];
        ps += trow[d]*W[2*D_ + d];
    }
    __syncthreads();   // scatter complete

    // denominator partials over first-occurrence slots
    float pd = 0.f;
    for (int i = tid; i < I_; i += 256) {
        if (g_first[b*I_ + i]) {
            float e = expf(sz[i]);
            g_pexp[(size_t)bt*I_ + i] = e;
            pd += e;
        }
    }

    red_s[tid] = ps; red_d[tid] = pd;
    __syncthreads();
    for (int s = 128; s > 0; s >>= 1) {
        if (tid < s) { red_s[tid] += red_s[tid+s]; red_d[tid] += red_d[tid+s]; }
        __syncthreads();
    }
    if (tid == 0) {
        float pg = 1.f / (1.f + expf(-(red_s[0] + bias[0])));
        float denom = (float)(V_ - g_ndist[b]) + red_d[0];
        g_pg[bt] = pg;
        g_invden[bt] = 1.f / denom;
        out_pg[bt] = pg;
    }
}

// ---- kernel 3: bulk streaming write of final + pointer ----------------------
__global__ void __launch_bounds__(256) big_kernel(
        const float4* __restrict__ gen,
        float4* __restrict__ fin,
        float4* __restrict__ ptr) {
    int bt    = blockIdx.x >> 2;
    int chunk = blockIdx.x & 3;
    float pg  = g_pg[bt];
    float inv = g_invden[bt];
    float q   = (1.f - pg) * inv;     // baseline contribution (z==0 slots)
    float4 pv = make_float4(inv, inv, inv, inv);
    size_t rowbase = (size_t)bt * V4_;
    int end = (chunk + 1) * CHUNK4_;
    for (int j = chunk*CHUNK4_ + threadIdx.x; j < end; j += 256) {
        size_t idx = rowbase + j;
        float4 g = __ldcs(&gen[idx]);          // streaming read, no reuse
        float4 f;
        f.x = fmaf(pg, g.x, q);
        f.y = fmaf(pg, g.y, q);
        f.z = fmaf(pg, g.z, q);
        f.w = fmaf(pg, g.w, q);
        fin[idx] = f;
        ptr[idx] = pv;
    }
}

// ---- kernel 4: sparse fixup of scattered vocab slots ------------------------
__global__ void fixup_kernel(const int* __restrict__ tokens,
                             const float* __restrict__ gen,
                             float* __restrict__ fin,
                             float* __restrict__ ptr) {
    int bt = blockIdx.x;
    int i  = threadIdx.x;            // 512 threads
    int b  = bt >> 9;
    if (g_first[b*I_ + i]) {
        int v = tokens[b*I_ + i];
        float inv = g_invden[bt];
        float pg  = g_pg[bt];
        float pval = g_pexp[(size_t)bt*I_ + i] * inv;
        size_t off = (size_t)bt*V_ + v;
        ptr[off] = pval;
        fin[off] = fmaf(pg, gen[off], (1.f - pg)*pval);
    }
}

// ---------------------------------------------------------------------------
extern "C" void kernel_launch(void* const* d_in, const int* in_sizes, int n_in,
                              void* d_out, int out_size) {
    const int*   inp_tokens = (const int*)  d_in[0];
    const float* tar_emb    = (const float*)d_in[1];
    const float* gen_out    = (const float*)d_in[2];
    const float* enc_out    = (const float*)d_in[3];
    const float* dec_state  = (const float*)d_in[4];
    const float* attn_heads = (const float*)d_in[5];
    const float* W_pgen     = (const float*)d_in[6];
    const float* b_pgen     = (const float*)d_in[7];

    float* out   = (float*)d_out;
    float* fin   = out;                    // (B,T,V)
    float* ptr   = out + BTV_;             // (B,T,V)
    float* pgout = out + 2*BTV_;           // (B,T)

    prep_kernel<<<B_, 512>>>(inp_tokens, enc_out, W_pgen);
    row_kernel<<<BT_, 256>>>(attn_heads, dec_state, tar_emb, W_pgen, b_pgen, pgout);
    big_kernel<<<BT_*4, 256>>>((const float4*)gen_out, (float4*)fin, (float4*)ptr);
    fixup_kernel<<<BT_, 512>>>(inp_tokens, gen_out, fin, ptr);
}

// round 2
// speedup vs baseline: 1.3338x; 1.3338x over previous
#include <cuda_runtime.h>
#include <math.h>

// Problem constants
#define B_ 4
#define T_ 512
#define I_ 512
#define H_ 8
#define D_ 512
#define V_ 32000
#define BT_ (B_*T_)                 // 2048
#define BI_ (B_*I_)                 // 2048
#define BTV_ ((size_t)BT_*V_)       // 65,536,000
#define V4_ (V_/4)                  // 8000 float4 per row
#define NCHUNK_ 4
#define CHUNK4_ (V4_/NCHUNK_)       // 2000 float4 per chunk
#define CHUNKV_ (V_/NCHUNK_)        // 8000 vocab slots per chunk

// ---------------- scratch (__device__ globals; no allocs allowed) -------------
__device__ float g_pexp[BT_*I_];    // exp(z) for first-occurrence slots
__device__ float g_eenc[BI_];       // enc[b,i,:] . W1
__device__ int   g_rep[BI_];        // index of first occurrence of token
__device__ int   g_first[BI_];      // 1 if first occurrence
__device__ int   g_ndist[B_];       // distinct token count per batch
__device__ float g_pg[BT_];         // p_gen
__device__ float g_invden[BT_];     // 1/softmax denominator

// ---------------- kernel 1: per-batch prep (dup grouping + e_enc) ------------
__global__ void prep_kernel(const int* __restrict__ tokens,
                            const float* __restrict__ enc,
                            const float* __restrict__ W) {
    int b = blockIdx.x;
    int tid = threadIdx.x;           // 512 threads
    __shared__ int stok[I_];
    __shared__ int cnt;
    stok[tid] = tokens[b*I_ + tid];
    if (tid == 0) cnt = 0;
    __syncthreads();

    // duplicate grouping: rep = smallest j with same token
    int tok = stok[tid];
    int rep = tid;
    for (int j = 0; j < tid; j++) {
        if (stok[j] == tok) { rep = j; break; }
    }
    g_rep[b*I_ + tid] = rep;
    int first = (rep == tid) ? 1 : 0;
    g_first[b*I_ + tid] = first;
    atomicAdd(&cnt, first);

    // e_enc: warp per row, coalesced
    int wid = tid >> 5, lane = tid & 31;
    for (int k = 0; k < 32; k++) {
        int row = wid*32 + k;
        const float* er = enc + ((size_t)b*I_ + row)*D_;
        float s = 0.f;
        #pragma unroll
        for (int d = lane; d < D_; d += 32) s += er[d]*W[d];
        #pragma unroll
        for (int off = 16; off > 0; off >>= 1)
            s += __shfl_down_sync(0xffffffffu, s, off);
        if (lane == 0) g_eenc[b*I_ + row] = s;
    }
    __syncthreads();
    if (tid == 0) g_ndist[b] = cnt;
}

// ---- kernel 2: per-(b,t) row: head-mean, p_gen, denom, exp table ------------
__global__ void __launch_bounds__(256) row_kernel(
        const float* __restrict__ attn_heads,
        const float* __restrict__ dec,
        const float* __restrict__ tar,
        const float* __restrict__ W,
        const float* __restrict__ bias,
        float* __restrict__ out_pg) {
    int bt = blockIdx.x;
    int b = bt >> 9, t = bt & 511;
    int tid = threadIdx.x;

    __shared__ float sattn[I_];
    __shared__ float sz[I_];
    __shared__ float red_s[256];
    __shared__ float red_d[256];

    const float* base = attn_heads + ((size_t)b*H_*T_*I_) + (size_t)t*I_;
    for (int i = tid; i < I_; i += 256) {
        float s = 0.f;
        #pragma unroll
        for (int h = 0; h < H_; h++) s += base[(size_t)h*T_*I_ + i];
        sattn[i] = s * 0.125f;
        sz[i] = 0.f;
    }
    __syncthreads();

    // scatter grouped z (collisions rare -> shared atomics cheap)
    for (int i = tid; i < I_; i += 256)
        atomicAdd(&sz[g_rep[b*I_ + i]], sattn[i]);

    // p_gen pre-activation partials (sattn read-only here, safe vs sz atomics)
    float ps = 0.f;
    const float* drow = dec + (size_t)bt*D_;
    const float* trow = tar + (size_t)bt*D_;
    for (int d = tid; d < D_; d += 256) {
        ps += sattn[d]*g_eenc[b*I_ + d];
        ps += drow[d]*W[D_ + d];
        ps += trow[d]*W[2*D_ + d];
    }
    __syncthreads();   // scatter complete

    // denominator partials over first-occurrence slots
    float pd = 0.f;
    for (int i = tid; i < I_; i += 256) {
        if (g_first[b*I_ + i]) {
            float e = expf(sz[i]);
            g_pexp[(size_t)bt*I_ + i] = e;
            pd += e;
        }
    }

    red_s[tid] = ps; red_d[tid] = pd;
    __syncthreads();
    for (int s = 128; s > 0; s >>= 1) {
        if (tid < s) { red_s[tid] += red_s[tid+s]; red_d[tid] += red_d[tid+s]; }
        __syncthreads();
    }
    if (tid == 0) {
        float pg = 1.f / (1.f + expf(-(red_s[0] + bias[0])));
        float denom = (float)(V_ - g_ndist[b]) + red_d[0];
        g_pg[bt] = pg;
        g_invden[bt] = 1.f / denom;
        out_pg[bt] = pg;
    }
}

// ---- kernel 3: bulk streaming write of final + pointer, fused sparse fixup --
__global__ void __launch_bounds__(256) big_kernel(
        const float4* __restrict__ gen4,
        float4* __restrict__ fin4,
        float4* __restrict__ ptr4,
        const int*   __restrict__ tokens,
        const float* __restrict__ gen,
        float*       __restrict__ fin,
        float*       __restrict__ ptr) {
    int bt    = blockIdx.x >> 2;
    int chunk = blockIdx.x & 3;
    int b     = bt >> 9;
    float pg  = g_pg[bt];
    float inv = g_invden[bt];
    float q   = (1.f - pg) * inv;     // baseline contribution (z==0 slots)
    float4 pv = make_float4(inv, inv, inv, inv);
    size_t rowbase = (size_t)bt * V4_;
    int end = (chunk + 1) * CHUNK4_;
    for (int j = chunk*CHUNK4_ + threadIdx.x; j < end; j += 256) {
        size_t idx = rowbase + j;
        float4 g = __ldcs(&gen4[idx]);         // streaming read, no reuse
        float4 f;
        f.x = fmaf(pg, g.x, q);
        f.y = fmaf(pg, g.y, q);
        f.z = fmaf(pg, g.z, q);
        f.w = fmaf(pg, g.w, q);
        fin4[idx] = f;
        ptr4[idx] = pv;
    }

    // Order bulk stores before sparse overwrites (intra-block memory barrier).
    __syncthreads();

    // Sparse fixup: overwrite the <=512 first-occurrence vocab slots that fall
    // inside this block's vocab range. Lines were just written by this block,
    // so these are L2 (often L1) hits. Tiny metadata arrays are fully cached.
    int vlo = chunk * CHUNKV_;
    int vhi = vlo + CHUNKV_;
    for (int i = threadIdx.x; i < I_; i += 256) {
        if (g_first[b*I_ + i]) {
            int v = tokens[b*I_ + i];
            if (v >= vlo && v < vhi) {
                float pval = g_pexp[(size_t)bt*I_ + i] * inv;
                size_t off = (size_t)bt*V_ + v;
                ptr[off] = pval;
                fin[off] = fmaf(pg, gen[off], (1.f - pg)*pval);
            }
        }
    }
}

// ---------------------------------------------------------------------------
extern "C" void kernel_launch(void* const* d_in, const int* in_sizes, int n_in,
                              void* d_out, int out_size) {
    const int*   inp_tokens = (const int*)  d_in[0];
    const float* tar_emb    = (const float*)d_in[1];
    const float* gen_out    = (const float*)d_in[2];
    const float* enc_out    = (const float*)d_in[3];
    const float* dec_state  = (const float*)d_in[4];
    const float* attn_heads = (const float*)d_in[5];
    const float* W_pgen     = (const float*)d_in[6];
    const float* b_pgen     = (const float*)d_in[7];

    float* out   = (float*)d_out;
    float* fin   = out;                    // (B,T,V)
    float* ptr   = out + BTV_;             // (B,T,V)
    float* pgout = out + 2*BTV_;           // (B,T)

    prep_kernel<<<B_, 512>>>(inp_tokens, enc_out, W_pgen);
    row_kernel<<<BT_, 256>>>(attn_heads, dec_state, tar_emb, W_pgen, b_pgen, pgout);
    big_kernel<<<BT_*NCHUNK_, 256>>>((const float4*)gen_out, (float4*)fin, (float4*)ptr,
                                     inp_tokens, gen_out, fin, ptr);
}

// round 3
// speedup vs baseline: 1.5084x; 1.1309x over previous
#include <cuda_runtime.h>
#include <math.h>

// Problem constants
#define B_ 4
#define T_ 512
#define I_ 512
#define H_ 8
#define D_ 512
#define V_ 32000
#define BT_ (B_*T_)                 // 2048
#define BI_ (B_*I_)                 // 2048
#define BTV_ ((size_t)BT_*V_)       // 65,536,000
#define V4_ (V_/4)                  // 8000 float4 per row
#define NCHUNK_ 4
#define CHUNK4_ (V4_/NCHUNK_)       // 2000 float4 per chunk
#define CHUNKV_ (V_/NCHUNK_)        // 8000 vocab slots per chunk

// ---------------- scratch (__device__ globals; no allocs allowed) -------------
__device__ float g_pexp[BT_*I_];    // exp(z) for first-occurrence slots
__device__ float g_eenc[BI_];       // enc[b,i,:] . W1
__device__ int   g_rep[BI_];        // index of first occurrence of token
__device__ int   g_first[BI_];      // 1 if first occurrence
__device__ int   g_ndist[B_];       // distinct token count per batch
__device__ float g_pg[BT_];         // p_gen
__device__ float g_invden[BT_];     // 1/softmax denominator

// ---------------- kernel 1a: per-batch duplicate grouping (tiny) -------------
__global__ void group_kernel(const int* __restrict__ tokens) {
    int b = blockIdx.x;
    int tid = threadIdx.x;           // 512 threads
    __shared__ int stok[I_];
    __shared__ int cnt;
    stok[tid] = tokens[b*I_ + tid];
    if (tid == 0) cnt = 0;
    __syncthreads();

    // rep = smallest j with same token
    int tok = stok[tid];
    int rep = tid;
    for (int j = 0; j < tid; j++) {
        if (stok[j] == tok) { rep = j; break; }
    }
    g_rep[b*I_ + tid] = rep;
    int first = (rep == tid) ? 1 : 0;
    g_first[b*I_ + tid] = first;
    atomicAdd(&cnt, first);
    __syncthreads();
    if (tid == 0) g_ndist[b] = cnt;
}

// ---------------- kernel 1b: e_enc = enc . W1, one warp per row --------------
__global__ void __launch_bounds__(256) eenc_kernel(const float* __restrict__ enc,
                                                   const float* __restrict__ W) {
    int row  = blockIdx.x * 8 + (threadIdx.x >> 5);   // global row in [0, BI_)
    int lane = threadIdx.x & 31;
    const float4* er = (const float4*)(enc + (size_t)row * D_);
    const float4* w4 = (const float4*)W;
    float s = 0.f;
    #pragma unroll
    for (int d = lane; d < D_/4; d += 32) {
        float4 e = er[d];
        float4 w = w4[d];
        s += e.x*w.x + e.y*w.y + e.z*w.z + e.w*w.w;
    }
    #pragma unroll
    for (int off = 16; off > 0; off >>= 1)
        s += __shfl_down_sync(0xffffffffu, s, off);
    if (lane == 0) g_eenc[row] = s;
}

// ---- kernel 2: per-(b,t) row: head-mean, p_gen, denom, exp table ------------
__global__ void __launch_bounds__(256) row_kernel(
        const float* __restrict__ attn_heads,
        const float* __restrict__ dec,
        const float* __restrict__ tar,
        const float* __restrict__ W,
        const float* __restrict__ bias,
        float* __restrict__ out_pg) {
    int bt = blockIdx.x;
    int b = bt >> 9, t = bt & 511;
    int tid = threadIdx.x;

    __shared__ float sattn[I_];
    __shared__ float sz[I_];
    __shared__ float red_s[256];
    __shared__ float red_d[256];

    const float* base = attn_heads + ((size_t)b*H_*T_*I_) + (size_t)t*I_;
    for (int i = tid; i < I_; i += 256) {
        float s = 0.f;
        #pragma unroll
        for (int h = 0; h < H_; h++) s += base[(size_t)h*T_*I_ + i];
        sattn[i] = s * 0.125f;
        sz[i] = 0.f;
    }
    __syncthreads();

    // scatter grouped z (collisions rare -> shared atomics cheap)
    for (int i = tid; i < I_; i += 256)
        atomicAdd(&sz[g_rep[b*I_ + i]], sattn[i]);

    // p_gen pre-activation partials (sattn read-only here, safe vs sz atomics)
    float ps = 0.f;
    const float* drow = dec + (size_t)bt*D_;
    const float* trow = tar + (size_t)bt*D_;
    for (int d = tid; d < D_; d += 256) {
        ps += sattn[d]*g_eenc[b*I_ + d];
        ps += drow[d]*W[D_ + d];
        ps += trow[d]*W[2*D_ + d];
    }
    __syncthreads();   // scatter complete

    // denominator partials over first-occurrence slots
    float pd = 0.f;
    for (int i = tid; i < I_; i += 256) {
        if (g_first[b*I_ + i]) {
            float e = expf(sz[i]);
            g_pexp[(size_t)bt*I_ + i] = e;
            pd += e;
        }
    }

    red_s[tid] = ps; red_d[tid] = pd;
    __syncthreads();
    for (int s = 128; s > 0; s >>= 1) {
        if (tid < s) { red_s[tid] += red_s[tid+s]; red_d[tid] += red_d[tid+s]; }
        __syncthreads();
    }
    if (tid == 0) {
        float pg = 1.f / (1.f + expf(-(red_s[0] + bias[0])));
        float denom = (float)(V_ - g_ndist[b]) + red_d[0];
        g_pg[bt] = pg;
        g_invden[bt] = 1.f / denom;
        out_pg[bt] = pg;
    }
}

// ---- kernel 3: bulk streaming write of final + pointer, fused sparse fixup --
__global__ void __launch_bounds__(256) big_kernel(
        const float4* __restrict__ gen4,
        float4* __restrict__ fin4,
        float4* __restrict__ ptr4,
        const int*   __restrict__ tokens,
        const float* __restrict__ gen,
        float*       __restrict__ fin,
        float*       __restrict__ ptr) {
    int bt    = blockIdx.x >> 2;
    int chunk = blockIdx.x & 3;
    int b     = bt >> 9;
    float pg  = g_pg[bt];
    float inv = g_invden[bt];
    float q   = (1.f - pg) * inv;     // baseline contribution (z==0 slots)
    float4 pv = make_float4(inv, inv, inv, inv);
    size_t rowbase = (size_t)bt * V4_;
    int end = (chunk + 1) * CHUNK4_;
    for (int j = chunk*CHUNK4_ + threadIdx.x; j < end; j += 256) {
        size_t idx = rowbase + j;
        float4 g = __ldcs(&gen4[idx]);         // streaming read, no reuse
        float4 f;
        f.x = fmaf(pg, g.x, q);
        f.y = fmaf(pg, g.y, q);
        f.z = fmaf(pg, g.z, q);
        f.w = fmaf(pg, g.w, q);
        __stcs(&fin4[idx], f);                 // streaming writes, no reuse
        __stcs(&ptr4[idx], pv);
    }

    // Order bulk stores before sparse overwrites (intra-block memory barrier).
    __syncthreads();

    // Sparse fixup: overwrite the <=512 first-occurrence vocab slots that fall
    // inside this block's vocab range.
    int vlo = chunk * CHUNKV_;
    int vhi = vlo + CHUNKV_;
    for (int i = threadIdx.x; i < I_; i += 256) {
        if (g_first[b*I_ + i]) {
            int v = tokens[b*I_ + i];
            if (v >= vlo && v < vhi) {
                float pval = g_pexp[(size_t)bt*I_ + i] * inv;
                size_t off = (size_t)bt*V_ + v;
                ptr[off] = pval;
                fin[off] = fmaf(pg, gen[off], (1.f - pg)*pval);
            }
        }
    }
}

// ---------------------------------------------------------------------------
extern "C" void kernel_launch(void* const* d_in, const int* in_sizes, int n_in,
                              void* d_out, int out_size) {
    const int*   inp_tokens = (const int*)  d_in[0];
    const float* tar_emb    = (const float*)d_in[1];
    const float* gen_out    = (const float*)d_in[2];
    const float* enc_out    = (const float*)d_in[3];
    const float* dec_state  = (const float*)d_in[4];
    const float* attn_heads = (const float*)d_in[5];
    const float* W_pgen     = (const float*)d_in[6];
    const float* b_pgen     = (const float*)d_in[7];

    float* out   = (float*)d_out;
    float* fin   = out;                    // (B,T,V)
    float* ptr   = out + BTV_;             // (B,T,V)
    float* pgout = out + 2*BTV_;           // (B,T)

    group_kernel<<<B_, 512>>>(inp_tokens);
    eenc_kernel<<<BI_/8, 256>>>(enc_out, W_pgen);
    row_kernel<<<BT_, 256>>>(attn_heads, dec_state, tar_emb, W_pgen, b_pgen, pgout);
    big_kernel<<<BT_*NCHUNK_, 256>>>((const float4*)gen_out, (float4*)fin, (float4*)ptr,
                                     inp_tokens, gen_out, fin, ptr);
}